// round 8
// baseline (speedup 1.0000x reference)
#include <cuda_runtime.h>
#include <cstdint>

// Geometric product in Cl(3,0,1): out[n,k] = sum_{i,j} a[n,i] b[n,j] C[i,j,k]
// Structure constants baked in at compile time (metric = 1,1,1,0).
//
// R7 = R6 (cp.async staged loads, swizzled smem, register-resident product)
// with the output smem round-trip removed: results go straight from
// registers to gmem via streaming STG.128 (__stcs). Drops the second
// __syncthreads (per-tile store bubble) and 8 smem instrs per thread,
// at the cost of strided store wavefronts (L1 has 3x headroom at 35.8%).
//
// [R8 = R7 resubmitted unchanged: R7 bench was an infra failure (container
//  hold failed twice); no kernel signal to act on.]

static __host__ __device__ constexpr int cayley_sign(int A, int B) {
    if (A & B & 8) return 0;            // degenerate generator e3 (metric 0)
    int s = 0;
    int sa = A >> 1;
    while (sa) {
        int x = sa & B;
        while (x) { s += 1; x &= (x - 1); }
        sa >>= 1;
    }
    return (s & 1) ? -1 : 1;
}

// Swizzled position for flat float4 index idx within a 1024-float4 tile:
//   r = idx>>2 (row), c = idx&3 (quad); pos = 4r | (c ^ ((r>>1)&3))
// Conflict-free for both unit-stride staging and per-row access.
static __device__ __forceinline__ int swz(int idx) {
    const int r = idx >> 2;
    const int c = idx & 3;
    return (r << 2) | (c ^ ((r >> 1) & 3));
}

static __device__ __forceinline__ uint32_t smem_u32(const void* p) {
    return (uint32_t)__cvta_generic_to_shared(p);
}

static __device__ __forceinline__ void cp_async16(uint32_t dst, const void* src) {
    asm volatile("cp.async.cg.shared.global [%0], [%1], 16;"
                 :: "r"(dst), "l"(src) : "memory");
}

__global__ void __launch_bounds__(256)
gp_kernel(const float4* __restrict__ a4,
          const float4* __restrict__ b4,
          float4* __restrict__ o4,
          int n_rows) {
    __shared__ __align__(16) float4 sa[1024];   // 16 KB
    __shared__ __align__(16) float4 sb[1024];   // 16 KB

    const int t     = threadIdx.x;
    const int base4 = blockIdx.x * 1024;
    const int row0  = blockIdx.x * 256;
    const bool full_tile = (row0 + 256 <= n_rows);

    // ---- Stage a and b: cp.async unit-stride gmem -> swizzled smem ----
    if (full_tile) {
        #pragma unroll
        for (int v = 0; v < 4; ++v) {
            const int idx = v * 256 + t;
            cp_async16(smem_u32(&sa[swz(idx)]), &a4[base4 + idx]);
            cp_async16(smem_u32(&sb[swz(idx)]), &b4[base4 + idx]);
        }
    } else {
        #pragma unroll
        for (int v = 0; v < 4; ++v) {
            const int idx = v * 256 + t;
            const int pos = swz(idx);
            if ((base4 + idx) < n_rows * 4) {
                cp_async16(smem_u32(&sa[pos]), &a4[base4 + idx]);
                cp_async16(smem_u32(&sb[pos]), &b4[base4 + idx]);
            } else {
                sa[pos] = make_float4(0.f, 0.f, 0.f, 0.f);
                sb[pos] = make_float4(0.f, 0.f, 0.f, 0.f);
            }
        }
    }
    asm volatile("cp.async.commit_group;" ::: "memory");
    asm volatile("cp.async.wait_group 0;" ::: "memory");
    __syncthreads();

    // ---- Each thread reads its own row (conflict-free via swizzle) ----
    float a[16], b[16];
    const int s = (t >> 1) & 3;
    #pragma unroll
    for (int v = 0; v < 4; ++v) {
        const int u = v ^ s;                       // physical quad holding logical quad v
        const float4 va = sa[(t << 2) | u];
        const float4 vb = sb[(t << 2) | u];
        a[v * 4 + 0] = va.x; a[v * 4 + 1] = va.y;
        a[v * 4 + 2] = va.z; a[v * 4 + 3] = va.w;
        b[v * 4 + 0] = vb.x; b[v * 4 + 1] = vb.y;
        b[v * 4 + 2] = vb.z; b[v * 4 + 3] = vb.w;
    }

    // ---- 192 straight-line FFMAs ----
    float c[16];
    #pragma unroll
    for (int k = 0; k < 16; ++k) c[k] = 0.0f;

    #pragma unroll
    for (int A = 0; A < 16; ++A) {
        #pragma unroll
        for (int B = 0; B < 16; ++B) {
            const int sg = cayley_sign(A, B);
            if (sg == 1) {
                c[A ^ B] = fmaf(a[A], b[B], c[A ^ B]);
            } else if (sg == -1) {
                c[A ^ B] = fmaf(-a[A], b[B], c[A ^ B]);
            }
        }
    }

    // ---- Direct streaming stores from registers (no smem round-trip,
    //      no second barrier). 4 STG.128 per thread, evict-first in L2. ----
    const int row = row0 + t;
    if (full_tile || row < n_rows) {
        const size_t ro = (size_t)row * 4;
        __stcs(&o4[ro + 0], make_float4(c[0],  c[1],  c[2],  c[3]));
        __stcs(&o4[ro + 1], make_float4(c[4],  c[5],  c[6],  c[7]));
        __stcs(&o4[ro + 2], make_float4(c[8],  c[9],  c[10], c[11]));
        __stcs(&o4[ro + 3], make_float4(c[12], c[13], c[14], c[15]));
    }
}

extern "C" void kernel_launch(void* const* d_in, const int* in_sizes, int n_in,
                              void* d_out, int out_size) {
    const float4* a4 = (const float4*)d_in[0];
    const float4* b4 = (const float4*)d_in[1];
    // d_in[2] is the Cayley tensor; values are baked in at compile time.
    float4* o4 = (float4*)d_out;

    const int n_rows = in_sizes[0] / 16;
    const int blocks = (n_rows + 255) / 256;
    gp_kernel<<<blocks, 256>>>(a4, b4, o4, n_rows);
}